// round 1
// baseline (speedup 1.0000x reference)
#include <cuda_runtime.h>

#define RES   256
#define FEAT  32
#define NPTS  524288

// Transposed planes: layout [plane][y*RES + x][channel] -> one tap = 128B line.
// 3 * 65536 * 32 * 4B = 24 MB static device scratch (allowed; not a runtime alloc).
__device__ float g_pt[3][RES * RES * FEAT];

__constant__ float c_off[12][2] = {
    {-1.0f,  0.0f}, {-0.5f,  0.0f}, { 0.5f,  0.0f}, { 1.0f,  0.0f},
    { 0.0f, -1.0f}, { 0.0f, -0.5f}, { 0.0f,  0.5f}, { 0.0f,  1.0f},
    { 0.5f,  0.5f}, { 0.5f, -0.5f}, {-0.5f,  0.5f}, {-0.5f, -0.5f}
};

// (C, H*W) -> (H*W, C) transpose through shared memory tile.
// grid: (RES*RES/32, 3), block: (32, 8)
__global__ void transpose_kernel(const float* __restrict__ p0,
                                 const float* __restrict__ p1,
                                 const float* __restrict__ p2) {
    __shared__ float tile[32][33];
    const float* src = (blockIdx.y == 0) ? p0 : (blockIdx.y == 1 ? p1 : p2);
    float* dst = g_pt[blockIdx.y];

    const int hw0 = blockIdx.x * 32;
    const int tx  = threadIdx.x;   // 0..31
    const int ty  = threadIdx.y;   // 0..7

    // read: coalesced along hw for each channel row
    #pragma unroll
    for (int c = ty; c < FEAT; c += 8)
        tile[c][tx] = src[c * (RES * RES) + hw0 + tx];
    __syncthreads();
    // write: coalesced along channel for each hw row
    #pragma unroll
    for (int row = ty; row < 32; row += 8)
        dst[(hw0 + row) * FEAT + tx] = tile[tx][row];
}

// Main sampling kernel: 8 lanes per point (float4 channel groups), 4 points/warp.
__global__ void __launch_bounds__(256) sample_kernel(
    const float* __restrict__ pts,
    const float* __restrict__ scales,
    const float* __restrict__ aabb,
    float* __restrict__ out)
{
    const int tid   = blockIdx.x * blockDim.x + threadIdx.x;
    const int lane  = tid & 31;
    const int grp   = lane >> 3;        // point within warp (0..3)
    const int cg    = lane & 7;         // channel group (0..7), 4 channels each
    const int p     = (tid >> 5) * 4 + grp;
    if (p >= NPTS) return;

    // aabb: row0 = max-ish corner (aabb[0]), row1 = other corner
    const float a00 = aabb[0], a01 = aabb[1], a02 = aabb[2];
    const float a10 = aabb[3], a11 = aabb[4], a12 = aabb[5];

    const float px = pts[p * 3 + 0];
    const float py = pts[p * 3 + 1];
    const float pz = pts[p * 3 + 2];

    float n[3];
    n[0] = (px - a00) * (2.0f / (a10 - a00)) - 1.0f;
    n[1] = (py - a01) * (2.0f / (a11 - a01)) - 1.0f;
    n[2] = (pz - a02) * (2.0f / (a12 - a02)) - 1.0f;

    float s[3];
    s[0] = scales[p * 3 + 0];
    s[1] = scales[p * 3 + 1];
    s[2] = scales[p * 3 + 2];

    const int qidx[3] = {0, 0, 1};
    const int ridx[3] = {1, 2, 2};

    float4 result;
    result.x = 1.0f; result.y = 1.0f; result.z = 1.0f; result.w = 1.0f;

    #pragma unroll
    for (int pl = 0; pl < 3; pl++) {
        const float bx  = n[qidx[pl]];
        const float by  = n[ridx[pl]];
        const float sxq = s[qidx[pl]];
        const float syr = s[ridx[pl]];
        const float4* __restrict__ plane = (const float4*)g_pt[pl];

        float4 acc;
        acc.x = 0.0f; acc.y = 0.0f; acc.z = 0.0f; acc.w = 0.0f;

        #pragma unroll
        for (int smp = 0; smp < 13; smp++) {
            float ox, oy;
            if (smp == 0) { ox = 0.0f; oy = 0.0f; }
            else          { ox = c_off[smp - 1][0]; oy = c_off[smp - 1][1]; }

            const float gx = bx + sxq * ox;
            const float gy = by + syr * oy;

            float x = fminf(fmaxf((gx + 1.0f) * 0.5f * (float)(RES - 1), 0.0f),
                            (float)(RES - 1));
            float y = fminf(fmaxf((gy + 1.0f) * 0.5f * (float)(RES - 1), 0.0f),
                            (float)(RES - 1));

            const float x0f = floorf(x);
            const float y0f = floorf(y);
            const float wx  = x - x0f;
            const float wy  = y - y0f;
            const int x0 = (int)x0f;
            const int y0 = (int)y0f;
            const int x1 = min(x0 + 1, RES - 1);
            const int y1 = min(y0 + 1, RES - 1);

            // float4-granular indices: cell * (FEAT/4) + cg
            const int r0 = y0 * RES;
            const int r1 = y1 * RES;
            const float4 f00 = plane[(r0 + x0) * (FEAT / 4) + cg];
            const float4 f10 = plane[(r0 + x1) * (FEAT / 4) + cg];
            const float4 f01 = plane[(r1 + x0) * (FEAT / 4) + cg];
            const float4 f11 = plane[(r1 + x1) * (FEAT / 4) + cg];

            const float w00 = (1.0f - wx) * (1.0f - wy);
            const float w10 = wx * (1.0f - wy);
            const float w01 = (1.0f - wx) * wy;
            const float w11 = wx * wy;

            acc.x += f00.x * w00 + f10.x * w10 + f01.x * w01 + f11.x * w11;
            acc.y += f00.y * w00 + f10.y * w10 + f01.y * w01 + f11.y * w11;
            acc.z += f00.z * w00 + f10.z * w10 + f01.z * w01 + f11.z * w11;
            acc.w += f00.w * w00 + f10.w * w10 + f01.w * w01 + f11.w * w11;
        }

        const float inv13 = 1.0f / 13.0f;
        result.x *= acc.x * inv13;
        result.y *= acc.y * inv13;
        result.z *= acc.z * inv13;
        result.w *= acc.w * inv13;
    }

    ((float4*)out)[p * (FEAT / 4) + cg] = result;
}

extern "C" void kernel_launch(void* const* d_in, const int* in_sizes, int n_in,
                              void* d_out, int out_size) {
    (void)in_sizes; (void)n_in; (void)out_size;
    const float* pts    = (const float*)d_in[0];
    // d_in[1] = timestamps (unused by reference)
    const float* scales = (const float*)d_in[2];
    const float* p0     = (const float*)d_in[3];
    const float* p1     = (const float*)d_in[4];
    const float* p2     = (const float*)d_in[5];
    const float* aabb   = (const float*)d_in[6];
    float* out          = (float*)d_out;

    dim3 tb(32, 8), tg(RES * RES / 32, 3);
    transpose_kernel<<<tg, tb>>>(p0, p1, p2);

    const int total_threads = NPTS * 8;           // 8 lanes per point
    sample_kernel<<<total_threads / 256, 256>>>(pts, scales, aabb, out);
}